// round 1
// baseline (speedup 1.0000x reference)
#include <cuda_runtime.h>
#include <math.h>

#define B_  2
#define T_  2048
#define D_  2048
#define H_  16
#define DH  128
#define MROWS (B_*T_)          // 4096
#define QKV_N (3*D_)           // 6144

// Scratch (device globals — no allocation allowed)
__device__ float g_qkv[(size_t)MROWS * QKV_N];   // ~100 MB
__device__ float g_o[(size_t)MROWS * D_];        // ~32 MB

// ---------------------------------------------------------------------------
// SGEMM + bias:  C[M,N] = A[M,K] @ B[K,N] + bias[N]
// 128x128 block tile, BK=16, 256 threads, 8x8 per-thread micro-tile.
// Requires M%128==0, N%128==0, K%16==0 (true for all uses here).
// ---------------------------------------------------------------------------
#define BM 128
#define BN 128
#define BK 16
#define TM 8
#define TN 8

__global__ __launch_bounds__(256) void sgemm_bias_kernel(
    const float* __restrict__ A, const float* __restrict__ Bm,
    const float* __restrict__ bias, float* __restrict__ C,
    int M, int N, int K)
{
    __shared__ float As[BK][BM];
    __shared__ float Bs[BK][BN];

    const int tid = threadIdx.x;
    const int tx  = tid & 15;
    const int ty  = tid >> 4;
    const int brow = blockIdx.y * BM;
    const int bcol = blockIdx.x * BN;

    float acc[TM][TN];
    #pragma unroll
    for (int i = 0; i < TM; i++)
        #pragma unroll
        for (int j = 0; j < TN; j++)
            acc[i][j] = 0.0f;

    const int a_r = tid >> 2;          // 0..63
    const int a_c = (tid & 3) * 4;     // 0,4,8,12
    const int b_r = tid >> 5;          // 0..7
    const int b_c = (tid & 31) * 4;    // 0..124

    for (int k0 = 0; k0 < K; k0 += BK) {
        #pragma unroll
        for (int i = 0; i < 2; i++) {
            int r = a_r + i * 64;
            float4 v = *(const float4*)&A[(size_t)(brow + r) * K + k0 + a_c];
            As[a_c + 0][r] = v.x;
            As[a_c + 1][r] = v.y;
            As[a_c + 2][r] = v.z;
            As[a_c + 3][r] = v.w;
        }
        #pragma unroll
        for (int i = 0; i < 2; i++) {
            int r = b_r + i * 8;
            *(float4*)&Bs[r][b_c] =
                *(const float4*)&Bm[(size_t)(k0 + r) * N + bcol + b_c];
        }
        __syncthreads();

        #pragma unroll
        for (int kk = 0; kk < BK; kk++) {
            float af[TM], bf[TN];
            *(float4*)&af[0] = *(const float4*)&As[kk][ty * TM];
            *(float4*)&af[4] = *(const float4*)&As[kk][ty * TM + 4];
            *(float4*)&bf[0] = *(const float4*)&Bs[kk][tx * TN];
            *(float4*)&bf[4] = *(const float4*)&Bs[kk][tx * TN + 4];
            #pragma unroll
            for (int i = 0; i < TM; i++)
                #pragma unroll
                for (int j = 0; j < TN; j++)
                    acc[i][j] += af[i] * bf[j];
        }
        __syncthreads();
    }

    #pragma unroll
    for (int i = 0; i < TM; i++) {
        const size_t row = (size_t)(brow + ty * TM + i);
        #pragma unroll
        for (int j = 0; j < TN; j += 4) {
            const int col = bcol + tx * TN + j;
            float4 o;
            o.x = acc[i][j + 0] + bias[col + 0];
            o.y = acc[i][j + 1] + bias[col + 1];
            o.z = acc[i][j + 2] + bias[col + 2];
            o.w = acc[i][j + 3] + bias[col + 3];
            *(float4*)&C[row * N + col] = o;
        }
    }
}

// ---------------------------------------------------------------------------
// Flash attention (fp32, causal, online softmax).
// One CTA per (b, h, 64-row q tile). 256 threads.
// ---------------------------------------------------------------------------
#define BQ  64
#define BKV 64
#define FLASH_SMEM_FLOATS (3 * BQ * DH + BQ * BKV + 2 * BQ)
#define FLASH_SMEM_BYTES  (FLASH_SMEM_FLOATS * 4)

__global__ __launch_bounds__(256, 1) void flash_kernel()
{
    extern __shared__ float sm[];
    float* Qs      = sm;                       // 64*128
    float* Ks      = Qs + BQ * DH;             // 64*128
    float* Vs      = Ks + BKV * DH;            // 64*128
    float* Ss      = Vs + BKV * DH;            // 64*64
    float* alpha_s = Ss + BQ * BKV;            // 64
    float* l_s     = alpha_s + BQ;             // 64

    const int q0  = blockIdx.x * BQ;
    const int h   = blockIdx.y;
    const int b   = blockIdx.z;
    const int tid = threadIdx.x;
    const int lane = tid & 31;
    const int wid  = tid >> 5;

    const size_t rowbase = (size_t)b * T_;
    const int qcol = h * DH;

    // Load Q tile (64x128)
    #pragma unroll
    for (int it = 0; it < 8; it++) {
        int idx = (tid + it * 256) * 4;        // 0..8188
        int r = idx >> 7;
        int c = idx & 127;
        *(float4*)&Qs[idx] =
            *(const float4*)&g_qkv[(rowbase + q0 + r) * (size_t)QKV_N + qcol + c];
    }

    // Online-softmax state: warp `wid` owns rows wid*8 .. wid*8+7
    float m_reg[8], l_reg[8];
    #pragma unroll
    for (int u = 0; u < 8; u++) { m_reg[u] = -INFINITY; l_reg[u] = 0.0f; }

    // PV accumulator: thread pr=tid/4 owns row pr, cols pc0..pc0+31
    const int pr  = tid >> 2;
    const int pc0 = (tid & 3) * 32;
    float4 o4[8];
    #pragma unroll
    for (int u = 0; u < 8; u++) o4[u] = make_float4(0.f, 0.f, 0.f, 0.f);

    const int ty = tid >> 4, tx = tid & 15;    // S-compute 16x16 grid
    const float scale = 0.08838834764831845f;  // 1/sqrt(128)

    const int ntiles = q0 / BKV + 1;
    for (int t = 0; t < ntiles; t++) {
        const int j0 = t * BKV;

        __syncthreads();   // previous iteration's consumers done with Ks/Vs/Ss
        #pragma unroll
        for (int it = 0; it < 8; it++) {
            int idx = (tid + it * 256) * 4;
            int r = idx >> 7;
            int c = idx & 127;
            const size_t base = (rowbase + j0 + r) * (size_t)QKV_N + qcol + c;
            *(float4*)&Ks[idx] = *(const float4*)&g_qkv[base + D_];
            *(float4*)&Vs[idx] = *(const float4*)&g_qkv[base + 2 * D_];
        }
        __syncthreads();

        // S = (Q K^T) * scale, causal mask; 4x4 micro-tile per thread
        float sacc[4][4];
        #pragma unroll
        for (int i = 0; i < 4; i++)
            #pragma unroll
            for (int j = 0; j < 4; j++)
                sacc[i][j] = 0.0f;

        for (int k4 = 0; k4 < DH / 4; k4++) {
            float4 qv[4], kv[4];
            #pragma unroll
            for (int i = 0; i < 4; i++)
                qv[i] = *(const float4*)&Qs[(ty * 4 + i) * DH + k4 * 4];
            #pragma unroll
            for (int j = 0; j < 4; j++)
                kv[j] = *(const float4*)&Ks[(tx * 4 + j) * DH + k4 * 4];
            #pragma unroll
            for (int i = 0; i < 4; i++)
                #pragma unroll
                for (int j = 0; j < 4; j++)
                    sacc[i][j] += qv[i].x * kv[j].x + qv[i].y * kv[j].y
                                + qv[i].z * kv[j].z + qv[i].w * kv[j].w;
        }
        #pragma unroll
        for (int i = 0; i < 4; i++) {
            const int rg = q0 + ty * 4 + i;
            #pragma unroll
            for (int j = 0; j < 4; j++) {
                const int cg = j0 + tx * 4 + j;
                float s = sacc[i][j] * scale;
                if (cg > rg) s = -1e30f;
                Ss[(ty * 4 + i) * BKV + tx * 4 + j] = s;
            }
        }
        __syncthreads();

        // Online softmax: warp wid handles its 8 rows
        #pragma unroll
        for (int u = 0; u < 8; u++) {
            const int r = wid * 8 + u;
            float s1 = Ss[r * BKV + lane];
            float s2 = Ss[r * BKV + 32 + lane];
            float mx = fmaxf(s1, s2);
            #pragma unroll
            for (int off = 16; off > 0; off >>= 1)
                mx = fmaxf(mx, __shfl_xor_sync(0xFFFFFFFFu, mx, off));
            const float mnew = fmaxf(m_reg[u], mx);
            const float p1 = __expf(s1 - mnew);
            const float p2 = __expf(s2 - mnew);
            Ss[r * BKV + lane]      = p1;
            Ss[r * BKV + 32 + lane] = p2;
            float ps = p1 + p2;
            #pragma unroll
            for (int off = 16; off > 0; off >>= 1)
                ps += __shfl_xor_sync(0xFFFFFFFFu, ps, off);
            const float alpha = __expf(m_reg[u] - mnew);
            l_reg[u] = l_reg[u] * alpha + ps;
            m_reg[u] = mnew;
            if (lane == 0) alpha_s[r] = alpha;
        }
        __syncthreads();

        // O = O*alpha + P @ V
        const float alpha = alpha_s[pr];
        #pragma unroll
        for (int u = 0; u < 8; u++) {
            o4[u].x *= alpha; o4[u].y *= alpha;
            o4[u].z *= alpha; o4[u].w *= alpha;
        }
        for (int j = 0; j < BKV; j++) {
            const float p = Ss[pr * BKV + j];
            const float4* vrow = (const float4*)&Vs[j * DH + pc0];
            #pragma unroll
            for (int u = 0; u < 8; u++) {
                const float4 v = vrow[u];
                o4[u].x += p * v.x; o4[u].y += p * v.y;
                o4[u].z += p * v.z; o4[u].w += p * v.w;
            }
        }
    }

    // publish l, normalize, write O as [B*T, D] with col = h*128 + c
    if (lane == 0) {
        #pragma unroll
        for (int u = 0; u < 8; u++) l_s[wid * 8 + u] = l_reg[u];
    }
    __syncthreads();
    const float linv = 1.0f / l_s[pr];
    const size_t orow = (rowbase + q0 + pr) * (size_t)D_ + h * DH + pc0;
    #pragma unroll
    for (int u = 0; u < 8; u++) {
        float4 o = o4[u];
        o.x *= linv; o.y *= linv; o.z *= linv; o.w *= linv;
        *(float4*)&g_o[orow + u * 4] = o;
    }
}

// ---------------------------------------------------------------------------
// Launch
// ---------------------------------------------------------------------------
extern "C" void kernel_launch(void* const* d_in, const int* in_sizes, int n_in,
                              void* d_out, int out_size)
{
    (void)in_sizes; (void)n_in; (void)out_size;
    const float* x    = (const float*)d_in[0];
    const float* Wqkv = (const float*)d_in[1];
    const float* bqkv = (const float*)d_in[2];
    const float* Wout = (const float*)d_in[3];
    const float* bout = (const float*)d_in[4];
    float* out = (float*)d_out;

    static float* qkv_ptr = nullptr;
    static float* o_ptr   = nullptr;
    static bool init_done = false;
    if (!init_done) {
        // First call is the (uncaptured) correctness run, so these immediate
        // host APIs never land inside graph capture.
        cudaFuncSetAttribute(flash_kernel,
                             cudaFuncAttributeMaxDynamicSharedMemorySize,
                             FLASH_SMEM_BYTES);
        void* p;
        cudaGetSymbolAddress(&p, g_qkv); qkv_ptr = (float*)p;
        cudaGetSymbolAddress(&p, g_o);   o_ptr   = (float*)p;
        init_done = true;
    }

    // 1) QKV = x @ Wqkv + bqkv      (4096 x 6144 x 2048)
    sgemm_bias_kernel<<<dim3(QKV_N / BN, MROWS / BM), 256>>>(
        x, Wqkv, bqkv, qkv_ptr, MROWS, QKV_N, D_);

    // 2) causal flash attention -> g_o (4096 x 2048)
    flash_kernel<<<dim3(T_ / BQ, H_, B_), 256, FLASH_SMEM_BYTES>>>();

    // 3) out = g_o @ Wout + bout    (4096 x 2048 x 2048)
    sgemm_bias_kernel<<<dim3(D_ / BN, MROWS / BM), 256>>>(
        o_ptr, Wout, bout, out, MROWS, D_, D_);
}

// round 3
// speedup vs baseline: 1.2895x; 1.2895x over previous
#include <cuda_runtime.h>
#include <math.h>
#include <stdint.h>

#define B_  2
#define T_  2048
#define D_  2048
#define H_  16
#define DH  128
#define MROWS (B_*T_)          // 4096
#define QKV_N (3*D_)           // 6144

// Scratch (device globals — no allocation allowed)
__device__ float g_qkv[(size_t)MROWS * QKV_N];    // ~100 MB
__device__ float g_o[(size_t)MROWS * D_];         // ~32 MB
__device__ float g_WqkvT[(size_t)QKV_N * D_];     // ~50 MB  (B^T, [N,K] K-contig)
__device__ float g_WoutT[(size_t)D_ * D_];        // ~16 MB

// ---------------------------------------------------------------------------
// Helpers
// ---------------------------------------------------------------------------
__device__ __forceinline__ void cp_async16(uint32_t s, const void* g) {
    asm volatile("cp.async.cg.shared.global [%0], [%1], 16;" :: "r"(s), "l"(g));
}
__device__ __forceinline__ void cp_commit() {
    asm volatile("cp.async.commit_group;" ::: "memory");
}
template <int N> __device__ __forceinline__ void cp_wait() {
    asm volatile("cp.async.wait_group %0;" :: "n"(N) : "memory");
}
__device__ __forceinline__ uint32_t smem_u32(const void* p) {
    uint32_t a;
    asm("{ .reg .u64 t; cvta.to.shared.u64 t, %1; cvt.u32.u64 %0, t; }"
        : "=r"(a) : "l"(p));
    return a;
}
__device__ __forceinline__ uint32_t f2tf32(float x) {
    uint32_t r;
    asm("cvt.rna.tf32.f32 %0, %1;" : "=r"(r) : "f"(x));
    return r;
}
__device__ __forceinline__ void mma_tf32(float c[4],
    uint32_t a0, uint32_t a1, uint32_t a2, uint32_t a3,
    uint32_t b0, uint32_t b1)
{
    asm volatile(
        "mma.sync.aligned.m16n8k8.row.col.f32.tf32.tf32.f32 "
        "{%0,%1,%2,%3}, {%4,%5,%6,%7}, {%8,%9}, {%0,%1,%2,%3};"
        : "+f"(c[0]), "+f"(c[1]), "+f"(c[2]), "+f"(c[3])
        : "r"(a0), "r"(a1), "r"(a2), "r"(a3), "r"(b0), "r"(b1));
}

// ---------------------------------------------------------------------------
// Weight transpose: At[N,K] = A[K,N]^T  (both dims % 32 == 0)
// ---------------------------------------------------------------------------
__global__ __launch_bounds__(256) void transpose_kernel(
    const float* __restrict__ A, float* __restrict__ At, int R, int C)
{
    __shared__ float tile[32][33];
    const int c = blockIdx.x * 32 + threadIdx.x;
    const int r = blockIdx.y * 32 + threadIdx.y;
    #pragma unroll
    for (int i = 0; i < 32; i += 8)
        tile[threadIdx.y + i][threadIdx.x] = A[(size_t)(r + i) * C + c];
    __syncthreads();
    const int tc = blockIdx.y * 32 + threadIdx.x;
    const int tr = blockIdx.x * 32 + threadIdx.y;
    #pragma unroll
    for (int i = 0; i < 32; i += 8)
        At[(size_t)(tr + i) * R + tc] = tile[threadIdx.x][threadIdx.y + i];
}

// ---------------------------------------------------------------------------
// tf32 mma.sync GEMM + bias:  C[M,N] = A[M,K] @ BT[N,K]^T + bias[N]
// CTA tile 128x128, BK=32, 2-stage cp.async double buffer, 256 threads.
// 8 warps: warp_m = wid%4 (32 rows), warp_n = wid/4 (64 cols).
// Warp tile 32x64 = 2 (M) x 8 (N) m16n8k8 mma tiles.
// SMEM: A [128 rows][36 floats], B^T [128 n-rows][36 floats] (pad 4 -> all LDS
// fragment loads are conflict-free: bank = (4*(lane>>2) + (lane&3)) % 32).
// ---------------------------------------------------------------------------
#define GBM 128
#define GBN 128
#define GBK 32
#define GSTRIDE 36
#define TILE_FLOATS (128 * GSTRIDE)                  // 4608
#define TILE_BYTES  (TILE_FLOATS * 4)                // 18432
#define STAGE_BYTES (2 * TILE_BYTES)                 // 36864 (A + B)
#define GEMM_SMEM   (2 * STAGE_BYTES)                // 73728

__device__ __forceinline__ void gemm_load_stage(
    const float* __restrict__ A, const float* __restrict__ BT, int K,
    uint32_t sa, uint32_t sb, int brow, int bcol, int k0, int tid)
{
    #pragma unroll
    for (int i = 0; i < 4; i++) {           // A: 128 rows x 128B
        int idx = tid + i * 256;            // 0..1023
        int row = idx >> 3;
        int c16 = idx & 7;
        cp_async16(sa + row * (GSTRIDE * 4) + c16 * 16,
                   &A[(size_t)(brow + row) * K + k0 + c16 * 4]);
    }
    #pragma unroll
    for (int i = 0; i < 4; i++) {           // B^T: 128 n-rows x 128B
        int idx = tid + i * 256;
        int row = idx >> 3;
        int c16 = idx & 7;
        cp_async16(sb + row * (GSTRIDE * 4) + c16 * 16,
                   &BT[(size_t)(bcol + row) * K + k0 + c16 * 4]);
    }
}

__global__ __launch_bounds__(256) void mma_gemm_bias(
    const float* __restrict__ A, const float* __restrict__ BT,
    const float* __restrict__ bias, float* __restrict__ C,
    int M, int N, int K)
{
    extern __shared__ float sm[];
    const int tid  = threadIdx.x;
    const int wid  = tid >> 5;
    const int lane = tid & 31;
    const int brow = blockIdx.y * GBM;
    const int bcol = blockIdx.x * GBN;
    const int warp_m = wid & 3;            // 0..3 -> rows warp_m*32
    const int warp_n = wid >> 2;           // 0..1 -> cols warp_n*64

    const uint32_t smem_base = smem_u32(sm);

    float acc[2][8][4];
    #pragma unroll
    for (int mt = 0; mt < 2; mt++)
        #pragma unroll
        for (int nt = 0; nt < 8; nt++)
            #pragma unroll
            for (int i = 0; i < 4; i++)
                acc[mt][nt][i] = 0.0f;

    const int KT = K / GBK;

    // Prologue: fill both stages
    gemm_load_stage(A, BT, K, smem_base, smem_base + TILE_BYTES,
                    brow, bcol, 0, tid);
    cp_commit();
    gemm_load_stage(A, BT, K, smem_base + STAGE_BYTES,
                    smem_base + STAGE_BYTES + TILE_BYTES,
                    brow, bcol, GBK, tid);
    cp_commit();

    const int qr = lane >> 2;              // 0..7
    const int qc = lane & 3;               // 0..3

    for (int kt = 0; kt < KT; kt++) {
        cp_wait<1>();
        __syncthreads();

        const int st = kt & 1;
        const float* As = sm + st * (STAGE_BYTES / 4);
        const float* Bs = As + TILE_FLOATS;

        #pragma unroll
        for (int k8 = 0; k8 < 4; k8++) {
            const int kk = k8 * 8;
            uint32_t af[2][4];
            #pragma unroll
            for (int mt = 0; mt < 2; mt++) {
                const int rb = warp_m * 32 + mt * 16 + qr;
                af[mt][0] = f2tf32(As[(rb    ) * GSTRIDE + kk + qc    ]);
                af[mt][1] = f2tf32(As[(rb + 8) * GSTRIDE + kk + qc    ]);
                af[mt][2] = f2tf32(As[(rb    ) * GSTRIDE + kk + qc + 4]);
                af[mt][3] = f2tf32(As[(rb + 8) * GSTRIDE + kk + qc + 4]);
            }
            #pragma unroll
            for (int nt = 0; nt < 8; nt++) {
                const int cb = warp_n * 64 + nt * 8 + qr;
                uint32_t b0 = f2tf32(Bs[cb * GSTRIDE + kk + qc    ]);
                uint32_t b1 = f2tf32(Bs[cb * GSTRIDE + kk + qc + 4]);
                #pragma unroll
                for (int mt = 0; mt < 2; mt++)
                    mma_tf32(acc[mt][nt], af[mt][0], af[mt][1],
                             af[mt][2], af[mt][3], b0, b1);
            }
        }
        __syncthreads();

        const int lkt = kt + 2;
        if (lkt < KT) {
            const uint32_t sa = smem_base + st * STAGE_BYTES;
            gemm_load_stage(A, BT, K, sa, sa + TILE_BYTES,
                            brow, bcol, lkt * GBK, tid);
        }
        cp_commit();
    }

    // Epilogue: C rows = brow + warp_m*32 + mt*16 + qr(+8); cols pairwise.
    #pragma unroll
    for (int mt = 0; mt < 2; mt++) {
        #pragma unroll
        for (int half = 0; half < 2; half++) {
            const int row = brow + warp_m * 32 + mt * 16 + qr + half * 8;
            #pragma unroll
            for (int nt = 0; nt < 8; nt++) {
                const int col = bcol + warp_n * 64 + nt * 8 + 2 * qc;
                float2 o;
                o.x = acc[mt][nt][half * 2 + 0] + bias[col + 0];
                o.y = acc[mt][nt][half * 2 + 1] + bias[col + 1];
                *(float2*)&C[(size_t)row * N + col] = o;
            }
        }
    }
}

// ---------------------------------------------------------------------------
// Flash attention (fp32, causal, online softmax). One CTA per (b, h, 64-row q).
// ---------------------------------------------------------------------------
#define BQ  64
#define BKV 64
#define FLASH_SMEM_FLOATS (3 * BQ * DH + BQ * BKV + 2 * BQ)
#define FLASH_SMEM_BYTES  (FLASH_SMEM_FLOATS * 4)

__global__ __launch_bounds__(256, 1) void flash_kernel()
{
    extern __shared__ float sm[];
    float* Qs      = sm;
    float* Ks      = Qs + BQ * DH;
    float* Vs      = Ks + BKV * DH;
    float* Ss      = Vs + BKV * DH;
    float* alpha_s = Ss + BQ * BKV;
    float* l_s     = alpha_s + BQ;

    const int q0  = blockIdx.x * BQ;
    const int h   = blockIdx.y;
    const int b   = blockIdx.z;
    const int tid = threadIdx.x;
    const int lane = tid & 31;
    const int wid  = tid >> 5;

    const size_t rowbase = (size_t)b * T_;
    const int qcol = h * DH;

    #pragma unroll
    for (int it = 0; it < 8; it++) {
        int idx = (tid + it * 256) * 4;
        int r = idx >> 7;
        int c = idx & 127;
        *(float4*)&Qs[idx] =
            *(const float4*)&g_qkv[(rowbase + q0 + r) * (size_t)QKV_N + qcol + c];
    }

    float m_reg[8], l_reg[8];
    #pragma unroll
    for (int u = 0; u < 8; u++) { m_reg[u] = -INFINITY; l_reg[u] = 0.0f; }

    const int pr  = tid >> 2;
    const int pc0 = (tid & 3) * 32;
    float4 o4[8];
    #pragma unroll
    for (int u = 0; u < 8; u++) o4[u] = make_float4(0.f, 0.f, 0.f, 0.f);

    const int ty = tid >> 4, tx = tid & 15;
    const float scale = 0.08838834764831845f;

    const int ntiles = q0 / BKV + 1;
    for (int t = 0; t < ntiles; t++) {
        const int j0 = t * BKV;

        __syncthreads();
        #pragma unroll
        for (int it = 0; it < 8; it++) {
            int idx = (tid + it * 256) * 4;
            int r = idx >> 7;
            int c = idx & 127;
            const size_t base = (rowbase + j0 + r) * (size_t)QKV_N + qcol + c;
            *(float4*)&Ks[idx] = *(const float4*)&g_qkv[base + D_];
            *(float4*)&Vs[idx] = *(const float4*)&g_qkv[base + 2 * D_];
        }
        __syncthreads();

        float sacc[4][4];
        #pragma unroll
        for (int i = 0; i < 4; i++)
            #pragma unroll
            for (int j = 0; j < 4; j++)
                sacc[i][j] = 0.0f;

        for (int k4 = 0; k4 < DH / 4; k4++) {
            float4 qv[4], kv[4];
            #pragma unroll
            for (int i = 0; i < 4; i++)
                qv[i] = *(const float4*)&Qs[(ty * 4 + i) * DH + k4 * 4];
            #pragma unroll
            for (int j = 0; j < 4; j++)
                kv[j] = *(const float4*)&Ks[(tx * 4 + j) * DH + k4 * 4];
            #pragma unroll
            for (int i = 0; i < 4; i++)
                #pragma unroll
                for (int j = 0; j < 4; j++)
                    sacc[i][j] += qv[i].x * kv[j].x + qv[i].y * kv[j].y
                                + qv[i].z * kv[j].z + qv[i].w * kv[j].w;
        }
        #pragma unroll
        for (int i = 0; i < 4; i++) {
            const int rg = q0 + ty * 4 + i;
            #pragma unroll
            for (int j = 0; j < 4; j++) {
                const int cg = j0 + tx * 4 + j;
                float s = sacc[i][j] * scale;
                if (cg > rg) s = -1e30f;
                Ss[(ty * 4 + i) * BKV + tx * 4 + j] = s;
            }
        }
        __syncthreads();

        #pragma unroll
        for (int u = 0; u < 8; u++) {
            const int r = wid * 8 + u;
            float s1 = Ss[r * BKV + lane];
            float s2 = Ss[r * BKV + 32 + lane];
            float mx = fmaxf(s1, s2);
            #pragma unroll
            for (int off = 16; off > 0; off >>= 1)
                mx = fmaxf(mx, __shfl_xor_sync(0xFFFFFFFFu, mx, off));
            const float mnew = fmaxf(m_reg[u], mx);
            const float p1 = __expf(s1 - mnew);
            const float p2 = __expf(s2 - mnew);
            Ss[r * BKV + lane]      = p1;
            Ss[r * BKV + 32 + lane] = p2;
            float ps = p1 + p2;
            #pragma unroll
            for (int off = 16; off > 0; off >>= 1)
                ps += __shfl_xor_sync(0xFFFFFFFFu, ps, off);
            const float alpha = __expf(m_reg[u] - mnew);
            l_reg[u] = l_reg[u] * alpha + ps;
            m_reg[u] = mnew;
            if (lane == 0) alpha_s[r] = alpha;
        }
        __syncthreads();

        const float alpha = alpha_s[pr];
        #pragma unroll
        for (int u = 0; u < 8; u++) {
            o4[u].x *= alpha; o4[u].y *= alpha;
            o4[u].z *= alpha; o4[u].w *= alpha;
        }
        for (int j = 0; j < BKV; j++) {
            const float p = Ss[pr * BKV + j];
            const float4* vrow = (const float4*)&Vs[j * DH + pc0];
            #pragma unroll
            for (int u = 0; u < 8; u++) {
                const float4 v = vrow[u];
                o4[u].x += p * v.x; o4[u].y += p * v.y;
                o4[u].z += p * v.z; o4[u].w += p * v.w;
            }
        }
    }

    if (lane == 0) {
        #pragma unroll
        for (int u = 0; u < 8; u++) l_s[wid * 8 + u] = l_reg[u];
    }
    __syncthreads();
    const float linv = 1.0f / l_s[pr];
    const size_t orow = (rowbase + q0 + pr) * (size_t)D_ + h * DH + pc0;
    #pragma unroll
    for (int u = 0; u < 8; u++) {
        float4 o = o4[u];
        o.x *= linv; o.y *= linv; o.z *= linv; o.w *= linv;
        *(float4*)&g_o[orow + u * 4] = o;
    }
}

// ---------------------------------------------------------------------------
// Launch
// ---------------------------------------------------------------------------
extern "C" void kernel_launch(void* const* d_in, const int* in_sizes, int n_in,
                              void* d_out, int out_size)
{
    (void)in_sizes; (void)n_in; (void)out_size;
    const float* x    = (const float*)d_in[0];
    const float* Wqkv = (const float*)d_in[1];
    const float* bqkv = (const float*)d_in[2];
    const float* Wout = (const float*)d_in[3];
    const float* bout = (const float*)d_in[4];
    float* out = (float*)d_out;

    static float *qkv_ptr = nullptr, *o_ptr = nullptr;
    static float *wqkvT_ptr = nullptr, *woutT_ptr = nullptr;
    static bool init_done = false;
    if (!init_done) {
        // First call is the (uncaptured) correctness run; these immediate host
        // APIs never land inside graph capture.
        cudaFuncSetAttribute(flash_kernel,
                             cudaFuncAttributeMaxDynamicSharedMemorySize,
                             FLASH_SMEM_BYTES);
        cudaFuncSetAttribute(mma_gemm_bias,
                             cudaFuncAttributeMaxDynamicSharedMemorySize,
                             GEMM_SMEM);
        void* p;
        cudaGetSymbolAddress(&p, g_qkv);   qkv_ptr   = (float*)p;
        cudaGetSymbolAddress(&p, g_o);     o_ptr     = (float*)p;
        cudaGetSymbolAddress(&p, g_WqkvT); wqkvT_ptr = (float*)p;
        cudaGetSymbolAddress(&p, g_WoutT); woutT_ptr = (float*)p;
        init_done = true;
    }

    // 0) Transpose weights to [N, K] K-contiguous for the mma B operand.
    transpose_kernel<<<dim3(QKV_N / 32, D_ / 32), dim3(32, 8)>>>(Wqkv, wqkvT_ptr, D_, QKV_N);
    transpose_kernel<<<dim3(D_ / 32, D_ / 32), dim3(32, 8)>>>(Wout, woutT_ptr, D_, D_);

    // 1) QKV = x @ Wqkv + bqkv   (4096 x 6144 x 2048, tf32 mma.sync)
    mma_gemm_bias<<<dim3(QKV_N / GBN, MROWS / GBM), 256, GEMM_SMEM>>>(
        x, wqkvT_ptr, bqkv, qkv_ptr, MROWS, QKV_N, D_);

    // 2) causal flash attention -> g_o (4096 x 2048)
    flash_kernel<<<dim3(T_ / BQ, H_, B_), 256, FLASH_SMEM_BYTES>>>();

    // 3) out = g_o @ Wout + bout  (4096 x 2048 x 2048, tf32 mma.sync)
    mma_gemm_bias<<<dim3(D_ / GBN, MROWS / GBM), 256, GEMM_SMEM>>>(
        o_ptr, woutT_ptr, bout, out, MROWS, D_, D_);
}

// round 4
// speedup vs baseline: 7.5808x; 5.8789x over previous
#include <cuda_runtime.h>
#include <math.h>
#include <stdint.h>

#define B_  2
#define T_  2048
#define D_  2048
#define H_  16
#define DH  128
#define MROWS (B_*T_)          // 4096
#define QKV_N (3*D_)           // 6144

// Scratch (device globals — no allocation allowed)
__device__ float g_qkv[(size_t)MROWS * QKV_N];    // ~100 MB (tf32-rounded)
__device__ float g_o[(size_t)MROWS * D_];         // ~32 MB  (tf32-rounded)
__device__ float g_xr[(size_t)MROWS * D_];        // ~32 MB  (x, tf32-rounded)
__device__ float g_WqkvT[(size_t)QKV_N * D_];     // ~50 MB  ([N,K], tf32-rounded)
__device__ float g_WoutT[(size_t)D_ * D_];        // ~16 MB

// ---------------------------------------------------------------------------
// Helpers
// ---------------------------------------------------------------------------
__device__ __forceinline__ void cp_async16(uint32_t s, const void* g) {
    asm volatile("cp.async.cg.shared.global [%0], [%1], 16;" :: "r"(s), "l"(g));
}
__device__ __forceinline__ void cp_commit() {
    asm volatile("cp.async.commit_group;" ::: "memory");
}
template <int N> __device__ __forceinline__ void cp_wait() {
    asm volatile("cp.async.wait_group %0;" :: "n"(N) : "memory");
}
__device__ __forceinline__ uint32_t smem_u32(const void* p) {
    uint32_t a;
    asm("{ .reg .u64 t; cvta.to.shared.u64 t, %1; cvt.u32.u64 %0, t; }"
        : "=r"(a) : "l"(p));
    return a;
}
__device__ __forceinline__ uint32_t f2tf32(float x) {
    uint32_t r;
    asm("cvt.rna.tf32.f32 %0, %1;" : "=r"(r) : "f"(x));
    return r;
}
__device__ __forceinline__ float roundtf(float x) {
    return __uint_as_float(f2tf32(x));
}
__device__ __forceinline__ void mma_tf32(float c[4],
    uint32_t a0, uint32_t a1, uint32_t a2, uint32_t a3,
    uint32_t b0, uint32_t b1)
{
    asm volatile(
        "mma.sync.aligned.m16n8k8.row.col.f32.tf32.tf32.f32 "
        "{%0,%1,%2,%3}, {%4,%5,%6,%7}, {%8,%9}, {%0,%1,%2,%3};"
        : "+f"(c[0]), "+f"(c[1]), "+f"(c[2]), "+f"(c[3])
        : "r"(a0), "r"(a1), "r"(a2), "r"(a3), "r"(b0), "r"(b1));
}

// ---------------------------------------------------------------------------
// Elementwise tf32 rounding (x pre-pass). n multiple of 1024.
// ---------------------------------------------------------------------------
__global__ __launch_bounds__(256) void round_tf32_kernel(
    const float* __restrict__ in, float* __restrict__ out)
{
    const int i = blockIdx.x * 256 + threadIdx.x;
    float4 v = ((const float4*)in)[i];
    v.x = roundtf(v.x); v.y = roundtf(v.y);
    v.z = roundtf(v.z); v.w = roundtf(v.w);
    ((float4*)out)[i] = v;
}

// ---------------------------------------------------------------------------
// Weight transpose + tf32 round: At[N,K] = round(A[K,N]^T)
// ---------------------------------------------------------------------------
__global__ __launch_bounds__(256) void transpose_kernel(
    const float* __restrict__ A, float* __restrict__ At, int R, int C)
{
    __shared__ float tile[32][33];
    const int c = blockIdx.x * 32 + threadIdx.x;
    const int r = blockIdx.y * 32 + threadIdx.y;
    #pragma unroll
    for (int i = 0; i < 32; i += 8)
        tile[threadIdx.y + i][threadIdx.x] = A[(size_t)(r + i) * C + c];
    __syncthreads();
    const int tc = blockIdx.y * 32 + threadIdx.x;
    const int tr = blockIdx.x * 32 + threadIdx.y;
    #pragma unroll
    for (int i = 0; i < 32; i += 8)
        At[(size_t)(tr + i) * R + tc] = roundtf(tile[threadIdx.x][threadIdx.y + i]);
}

// ---------------------------------------------------------------------------
// tf32 mma.sync GEMM + bias: C[M,N] = A[M,K] @ BT[N,K]^T + bias[N]
// CTA 256x128, BK=32, 2-stage cp.async, 512 threads (16 warps, 8m x 2n).
// Warp tile 32x64 = 2(m) x 8(n) m16n8k8. Inputs pre-rounded to tf32 -> no cvt.
// SMEM row stride 36 floats -> conflict-free fragment LDS.
// ---------------------------------------------------------------------------
#define GBM 256
#define GBN 128
#define GBK 32
#define GSTRIDE 36
#define A_TILE_FLOATS (256 * GSTRIDE)                // 9216
#define B_TILE_FLOATS (128 * GSTRIDE)                // 4608
#define STAGE_FLOATS  (A_TILE_FLOATS + B_TILE_FLOATS)// 13824
#define GEMM_SMEM     (2 * STAGE_FLOATS * 4)         // 110592

__device__ __forceinline__ void gemm_load_stage(
    const float* __restrict__ A, const float* __restrict__ BT, int K,
    uint32_t sa, uint32_t sb, int brow, int bcol, int k0, int tid)
{
    #pragma unroll
    for (int i = 0; i < 4; i++) {           // A: 256 rows x 128B
        int idx = tid + i * 512;            // 0..2047
        int row = idx >> 3;
        int c16 = idx & 7;
        cp_async16(sa + row * (GSTRIDE * 4) + c16 * 16,
                   &A[(size_t)(brow + row) * K + k0 + c16 * 4]);
    }
    #pragma unroll
    for (int i = 0; i < 2; i++) {           // B^T: 128 n-rows x 128B
        int idx = tid + i * 512;            // 0..1023
        int row = idx >> 3;
        int c16 = idx & 7;
        cp_async16(sb + row * (GSTRIDE * 4) + c16 * 16,
                   &BT[(size_t)(bcol + row) * K + k0 + c16 * 4]);
    }
}

template <bool ROUND_OUT>
__global__ __launch_bounds__(512) void mma_gemm_bias(
    const float* __restrict__ A, const float* __restrict__ BT,
    const float* __restrict__ bias, float* __restrict__ C,
    int M, int N, int K)
{
    extern __shared__ float sm[];
    const int tid  = threadIdx.x;
    const int wid  = tid >> 5;
    const int lane = tid & 31;
    const int brow = blockIdx.y * GBM;
    const int bcol = blockIdx.x * GBN;
    const int warp_m = wid & 7;            // rows warp_m*32
    const int warp_n = wid >> 3;           // cols warp_n*64

    const uint32_t smem_base = smem_u32(sm);

    float acc[2][8][4];
    #pragma unroll
    for (int mt = 0; mt < 2; mt++)
        #pragma unroll
        for (int nt = 0; nt < 8; nt++)
            #pragma unroll
            for (int i = 0; i < 4; i++)
                acc[mt][nt][i] = 0.0f;

    const int KT = K / GBK;

    gemm_load_stage(A, BT, K, smem_base, smem_base + A_TILE_FLOATS * 4,
                    brow, bcol, 0, tid);
    cp_commit();
    gemm_load_stage(A, BT, K, smem_base + STAGE_FLOATS * 4,
                    smem_base + (STAGE_FLOATS + A_TILE_FLOATS) * 4,
                    brow, bcol, GBK, tid);
    cp_commit();

    const int qr = lane >> 2;
    const int qc = lane & 3;

    for (int kt = 0; kt < KT; kt++) {
        cp_wait<1>();
        __syncthreads();

        const int st = kt & 1;
        const uint32_t* Au = (const uint32_t*)(sm + st * STAGE_FLOATS);
        const uint32_t* Bu = Au + A_TILE_FLOATS;

        #pragma unroll
        for (int k8 = 0; k8 < 4; k8++) {
            const int kk = k8 * 8;
            uint32_t af[2][4];
            #pragma unroll
            for (int mt = 0; mt < 2; mt++) {
                const int rb = warp_m * 32 + mt * 16 + qr;
                af[mt][0] = Au[(rb    ) * GSTRIDE + kk + qc    ];
                af[mt][1] = Au[(rb + 8) * GSTRIDE + kk + qc    ];
                af[mt][2] = Au[(rb    ) * GSTRIDE + kk + qc + 4];
                af[mt][3] = Au[(rb + 8) * GSTRIDE + kk + qc + 4];
            }
            #pragma unroll
            for (int nt = 0; nt < 8; nt++) {
                const int cb = warp_n * 64 + nt * 8 + qr;
                uint32_t b0 = Bu[cb * GSTRIDE + kk + qc    ];
                uint32_t b1 = Bu[cb * GSTRIDE + kk + qc + 4];
                #pragma unroll
                for (int mt = 0; mt < 2; mt++)
                    mma_tf32(acc[mt][nt], af[mt][0], af[mt][1],
                             af[mt][2], af[mt][3], b0, b1);
            }
        }
        __syncthreads();

        const int lkt = kt + 2;
        if (lkt < KT) {
            const uint32_t sa = smem_base + st * STAGE_FLOATS * 4;
            gemm_load_stage(A, BT, K, sa, sa + A_TILE_FLOATS * 4,
                            brow, bcol, lkt * GBK, tid);
        }
        cp_commit();
    }

    #pragma unroll
    for (int mt = 0; mt < 2; mt++) {
        #pragma unroll
        for (int half = 0; half < 2; half++) {
            const int row = brow + warp_m * 32 + mt * 16 + qr + half * 8;
            #pragma unroll
            for (int nt = 0; nt < 8; nt++) {
                const int col = bcol + warp_n * 64 + nt * 8 + 2 * qc;
                float2 o;
                o.x = acc[mt][nt][half * 2 + 0] + bias[col + 0];
                o.y = acc[mt][nt][half * 2 + 1] + bias[col + 1];
                if (ROUND_OUT) { o.x = roundtf(o.x); o.y = roundtf(o.y); }
                *(float2*)&C[(size_t)row * N + col] = o;
            }
        }
    }
}

// ---------------------------------------------------------------------------
// Tensor-core flash attention (tf32 mma, causal, register softmax).
// CTA: 128 q-rows, 256 threads (8 warps x 16 rows). KV tiles of 64,
// double-buffered cp.async. Q stride 132, K stride 132, V stride 136
// (all fragment LDS conflict-free). Scale folded into exp().
// ---------------------------------------------------------------------------
#define FBQ  128
#define QSTR 132
#define KSTR 132
#define VSTR 136
#define Q_FLOATS    (FBQ * QSTR)                 // 16896
#define KV_STAGE_FL (64 * KSTR + 64 * VSTR)      // 17152
#define FLASH_SMEM  ((Q_FLOATS + 2 * KV_STAGE_FL) * 4)   // 204800

__device__ __forceinline__ void load_kv_tile(
    uint32_t kbase, uint32_t vbase, size_t rowbase, int j0, int qcol, int tid)
{
    #pragma unroll
    for (int i = 0; i < 8; i++) {
        int idx = tid + i * 256;          // 0..2047
        int r = idx >> 5;                 // 0..63
        int c4 = idx & 31;                // *4 floats
        cp_async16(kbase + (r * KSTR + c4 * 4) * 4,
                   &g_qkv[(rowbase + j0 + r) * (size_t)QKV_N + qcol + D_ + c4 * 4]);
    }
    #pragma unroll
    for (int i = 0; i < 8; i++) {
        int idx = tid + i * 256;
        int r = idx >> 5;
        int c4 = idx & 31;
        cp_async16(vbase + (r * VSTR + c4 * 4) * 4,
                   &g_qkv[(rowbase + j0 + r) * (size_t)QKV_N + qcol + 2 * D_ + c4 * 4]);
    }
}

__global__ __launch_bounds__(256, 1) void flash_mma_kernel()
{
    extern __shared__ float sm[];
    const int qi  = (gridDim.x - 1) - blockIdx.x;   // big q-blocks first
    const int q0  = qi * FBQ;
    const int h   = blockIdx.y;
    const int b   = blockIdx.z;
    const int tid = threadIdx.x;
    const int lane = tid & 31;
    const int wid  = tid >> 5;
    const int qr = lane >> 2;
    const int qc = lane & 3;

    const size_t rowbase = (size_t)b * T_;
    const int qcol = h * DH;
    const float SCALE = 0.08838834764831845f;   // 1/sqrt(128)

    // Q tile -> smem (already tf32-rounded in gmem)
    #pragma unroll
    for (int i = 0; i < 16; i++) {
        int idx = tid + i * 256;          // 0..4095 float4
        int r = idx >> 5;
        int c4 = idx & 31;
        *(float4*)&sm[r * QSTR + c4 * 4] =
            *(const float4*)&g_qkv[(rowbase + q0 + r) * (size_t)QKV_N + qcol + c4 * 4];
    }

    const uint32_t smem_base = smem_u32(sm);
    const int ntile = 2 * qi + 2;

    // Prologue KV loads
    {
        uint32_t s0 = smem_base + Q_FLOATS * 4;
        load_kv_tile(s0, s0 + 64 * KSTR * 4, rowbase, 0, qcol, tid);
        cp_commit();
        if (ntile > 1) {
            uint32_t s1 = smem_base + (Q_FLOATS + KV_STAGE_FL) * 4;
            load_kv_tile(s1, s1 + 64 * KSTR * 4, rowbase, 64, qcol, tid);
        }
        cp_commit();
    }

    float oacc[16][4];
    #pragma unroll
    for (int n = 0; n < 16; n++)
        #pragma unroll
        for (int i = 0; i < 4; i++) oacc[n][i] = 0.0f;
    float mrow0 = -3.0e38f, mrow1 = -3.0e38f;
    float lrow0 = 0.0f, lrow1 = 0.0f;

    const int mloc = wid * 16;
    const uint32_t* Qu = (const uint32_t*)sm;
    const int s1l = (lane & ~3) | (qc >> 1);
    const int s2l = s1l | 2;
    const bool odd = qc & 1;

    for (int t = 0; t < ntile; t++) {
        cp_wait<1>();
        __syncthreads();

        const uint32_t* Ku = (const uint32_t*)(sm + Q_FLOATS + (t & 1) * KV_STAGE_FL);
        const uint32_t* Vu = Ku + 64 * KSTR;

        // ---- S = Q @ K^T (raw, scale folded into exp) ----
        float sacc[8][4];
        #pragma unroll
        for (int n = 0; n < 8; n++)
            #pragma unroll
            for (int i = 0; i < 4; i++) sacc[n][i] = 0.0f;

        #pragma unroll
        for (int k8 = 0; k8 < 16; k8++) {
            const int kk = k8 * 8;
            uint32_t a0 = Qu[(mloc + qr    ) * QSTR + kk + qc    ];
            uint32_t a1 = Qu[(mloc + qr + 8) * QSTR + kk + qc    ];
            uint32_t a2 = Qu[(mloc + qr    ) * QSTR + kk + qc + 4];
            uint32_t a3 = Qu[(mloc + qr + 8) * QSTR + kk + qc + 4];
            #pragma unroll
            for (int nt = 0; nt < 8; nt++) {
                uint32_t b0 = Ku[(nt * 8 + qr) * KSTR + kk + qc    ];
                uint32_t b1 = Ku[(nt * 8 + qr) * KSTR + kk + qc + 4];
                mma_tf32(sacc[nt], a0, a1, a2, a3, b0, b1);
            }
        }

        // ---- causal mask (only last 2 tiles touch the diagonal) ----
        if (t >= ntile - 2) {
            const int j0 = t * 64;
            const int rg0 = q0 + mloc + qr;
            const int rg1 = rg0 + 8;
            #pragma unroll
            for (int nt = 0; nt < 8; nt++) {
                const int cg = j0 + nt * 8 + 2 * qc;
                if (cg     > rg0) sacc[nt][0] = -1.0e30f;
                if (cg + 1 > rg0) sacc[nt][1] = -1.0e30f;
                if (cg     > rg1) sacc[nt][2] = -1.0e30f;
                if (cg + 1 > rg1) sacc[nt][3] = -1.0e30f;
            }
        }

        // ---- online softmax (per-row, quad lanes) ----
        float mx0 = -3.0e38f, mx1 = -3.0e38f;
        #pragma unroll
        for (int nt = 0; nt < 8; nt++) {
            mx0 = fmaxf(mx0, fmaxf(sacc[nt][0], sacc[nt][1]));
            mx1 = fmaxf(mx1, fmaxf(sacc[nt][2], sacc[nt][3]));
        }
        mx0 = fmaxf(mx0, __shfl_xor_sync(0xFFFFFFFFu, mx0, 1));
        mx0 = fmaxf(mx0, __shfl_xor_sync(0xFFFFFFFFu, mx0, 2));
        mx1 = fmaxf(mx1, __shfl_xor_sync(0xFFFFFFFFu, mx1, 1));
        mx1 = fmaxf(mx1, __shfl_xor_sync(0xFFFFFFFFu, mx1, 2));
        const float mn0 = fmaxf(mrow0, mx0);
        const float mn1 = fmaxf(mrow1, mx1);
        const float al0 = __expf((mrow0 - mn0) * SCALE);
        const float al1 = __expf((mrow1 - mn1) * SCALE);
        mrow0 = mn0; mrow1 = mn1;

        uint32_t pacc[8][4];
        float ps0 = 0.0f, ps1 = 0.0f;
        #pragma unroll
        for (int nt = 0; nt < 8; nt++) {
            float p0 = __expf((sacc[nt][0] - mn0) * SCALE);
            float p1 = __expf((sacc[nt][1] - mn0) * SCALE);
            float p2 = __expf((sacc[nt][2] - mn1) * SCALE);
            float p3 = __expf((sacc[nt][3] - mn1) * SCALE);
            ps0 += p0 + p1;
            ps1 += p2 + p3;
            pacc[nt][0] = f2tf32(p0);
            pacc[nt][1] = f2tf32(p1);
            pacc[nt][2] = f2tf32(p2);
            pacc[nt][3] = f2tf32(p3);
        }
        ps0 += __shfl_xor_sync(0xFFFFFFFFu, ps0, 1);
        ps0 += __shfl_xor_sync(0xFFFFFFFFu, ps0, 2);
        ps1 += __shfl_xor_sync(0xFFFFFFFFu, ps1, 1);
        ps1 += __shfl_xor_sync(0xFFFFFFFFu, ps1, 2);
        lrow0 = lrow0 * al0 + ps0;
        lrow1 = lrow1 * al1 + ps1;

        #pragma unroll
        for (int n = 0; n < 16; n++) {
            oacc[n][0] *= al0; oacc[n][1] *= al0;
            oacc[n][2] *= al1; oacc[n][3] *= al1;
        }

        // ---- O += P @ V ----
        #pragma unroll
        for (int ks = 0; ks < 8; ks++) {
            uint32_t x0 = __shfl_sync(0xFFFFFFFFu, pacc[ks][0], s1l);
            uint32_t x1 = __shfl_sync(0xFFFFFFFFu, pacc[ks][1], s1l);
            uint32_t x2 = __shfl_sync(0xFFFFFFFFu, pacc[ks][2], s1l);
            uint32_t x3 = __shfl_sync(0xFFFFFFFFu, pacc[ks][3], s1l);
            uint32_t y0 = __shfl_sync(0xFFFFFFFFu, pacc[ks][0], s2l);
            uint32_t y1 = __shfl_sync(0xFFFFFFFFu, pacc[ks][1], s2l);
            uint32_t y2 = __shfl_sync(0xFFFFFFFFu, pacc[ks][2], s2l);
            uint32_t y3 = __shfl_sync(0xFFFFFFFFu, pacc[ks][3], s2l);
            uint32_t a0 = odd ? x1 : x0;
            uint32_t a1 = odd ? x3 : x2;
            uint32_t a2 = odd ? y1 : y0;
            uint32_t a3 = odd ? y3 : y2;
            #pragma unroll
            for (int ntd = 0; ntd < 16; ntd++) {
                uint32_t b0 = Vu[(ks * 8 + qc    ) * VSTR + ntd * 8 + qr];
                uint32_t b1 = Vu[(ks * 8 + qc + 4) * VSTR + ntd * 8 + qr];
                mma_tf32(oacc[ntd], a0, a1, a2, a3, b0, b1);
            }
        }

        __syncthreads();
        if (t + 2 < ntile) {
            uint32_t sb = smem_base + (Q_FLOATS + (t & 1) * KV_STAGE_FL) * 4;
            load_kv_tile(sb, sb + 64 * KSTR * 4, rowbase, (t + 2) * 64, qcol, tid);
        }
        cp_commit();
    }

    // ---- epilogue: normalize, tf32-round (feeds out-proj GEMM), store ----
    const float li0 = 1.0f / lrow0;
    const float li1 = 1.0f / lrow1;
    const int r0 = q0 + mloc + qr;
    const int r1 = r0 + 8;
    #pragma unroll
    for (int ntd = 0; ntd < 16; ntd++) {
        const int col = qcol + ntd * 8 + 2 * qc;
        float2 v0, v1;
        v0.x = roundtf(oacc[ntd][0] * li0);
        v0.y = roundtf(oacc[ntd][1] * li0);
        v1.x = roundtf(oacc[ntd][2] * li1);
        v1.y = roundtf(oacc[ntd][3] * li1);
        *(float2*)&g_o[(rowbase + r0) * (size_t)D_ + col] = v0;
        *(float2*)&g_o[(rowbase + r1) * (size_t)D_ + col] = v1;
    }
}

// ---------------------------------------------------------------------------
// Launch
// ---------------------------------------------------------------------------
extern "C" void kernel_launch(void* const* d_in, const int* in_sizes, int n_in,
                              void* d_out, int out_size)
{
    (void)in_sizes; (void)n_in; (void)out_size;
    const float* x    = (const float*)d_in[0];
    const float* Wqkv = (const float*)d_in[1];
    const float* bqkv = (const float*)d_in[2];
    const float* Wout = (const float*)d_in[3];
    const float* bout = (const float*)d_in[4];
    float* out = (float*)d_out;

    static float *qkv_ptr = nullptr, *o_ptr = nullptr, *xr_ptr = nullptr;
    static float *wqkvT_ptr = nullptr, *woutT_ptr = nullptr;
    static bool init_done = false;
    if (!init_done) {
        // First call is the (uncaptured) correctness run; these immediate host
        // APIs never land inside graph capture.
        cudaFuncSetAttribute(flash_mma_kernel,
                             cudaFuncAttributeMaxDynamicSharedMemorySize,
                             FLASH_SMEM);
        cudaFuncSetAttribute(mma_gemm_bias<true>,
                             cudaFuncAttributeMaxDynamicSharedMemorySize,
                             GEMM_SMEM);
        cudaFuncSetAttribute(mma_gemm_bias<false>,
                             cudaFuncAttributeMaxDynamicSharedMemorySize,
                             GEMM_SMEM);
        void* p;
        cudaGetSymbolAddress(&p, g_qkv);   qkv_ptr   = (float*)p;
        cudaGetSymbolAddress(&p, g_o);     o_ptr     = (float*)p;
        cudaGetSymbolAddress(&p, g_xr);    xr_ptr    = (float*)p;
        cudaGetSymbolAddress(&p, g_WqkvT); wqkvT_ptr = (float*)p;
        cudaGetSymbolAddress(&p, g_WoutT); woutT_ptr = (float*)p;
        init_done = true;
    }

    // 0) tf32 pre-rounding: x copy; weights transposed+rounded.
    round_tf32_kernel<<<(MROWS * (size_t)D_ / 4) / 256, 256>>>(x, xr_ptr);
    transpose_kernel<<<dim3(QKV_N / 32, D_ / 32), dim3(32, 8)>>>(Wqkv, wqkvT_ptr, D_, QKV_N);
    transpose_kernel<<<dim3(D_ / 32, D_ / 32), dim3(32, 8)>>>(Wout, woutT_ptr, D_, D_);

    // 1) QKV = x @ Wqkv + bqkv (tf32 mma; output tf32-rounded for attention)
    mma_gemm_bias<true><<<dim3(QKV_N / GBN, MROWS / GBM), 512, GEMM_SMEM>>>(
        xr_ptr, wqkvT_ptr, bqkv, qkv_ptr, MROWS, QKV_N, D_);

    // 2) causal flash attention (tensor cores) -> g_o (tf32-rounded)
    flash_mma_kernel<<<dim3(T_ / FBQ, H_, B_), 256, FLASH_SMEM>>>();

    // 3) out = g_o @ Wout + bout (tf32 mma, fp32 output)
    mma_gemm_bias<false><<<dim3(D_ / GBN, MROWS / GBM), 512, GEMM_SMEM>>>(
        o_ptr, woutT_ptr, bout, out, MROWS, D_, D_);
}